// round 11
// baseline (speedup 1.0000x reference)
#include <cuda_runtime.h>
#include <cuda_bf16.h>
#include <math.h>
#include <stdint.h>

// ---------------------------------------------------------------------------
// Problem constants
// ---------------------------------------------------------------------------
#define B_    2
#define T_    2048
#define D_    2048
#define H_    16
#define KV_   4
#define HD_   128
#define NREP_ 4
#define M_    (B_ * T_)          // 4096 rows

// ---------------------------------------------------------------------------
// Static device scratch (no cudaMalloc allowed)
// ---------------------------------------------------------------------------
__device__ float g_q [(size_t)M_ * (H_ * HD_)];
__device__ float g_k [(size_t)M_ * (KV_ * HD_)];
__device__ float g_v [(size_t)M_ * (KV_ * HD_)];
__device__ float g_ao[(size_t)M_ * (H_ * HD_)];
__device__ float g_cos[T_ * 64];
__device__ float g_sin[T_ * 64];

// bf16 split operands (hi + lo decomposition for compensated MMA)
__device__ __nv_bfloat16 g_xhi [(size_t)M_ * D_];
__device__ __nv_bfloat16 g_xlo [(size_t)M_ * D_];
__device__ __nv_bfloat16 g_aohi[(size_t)M_ * D_];
__device__ __nv_bfloat16 g_aolo[(size_t)M_ * D_];
// transposed weights Wt[N][K], split
__device__ __nv_bfloat16 g_wqt_hi[(size_t)(H_ * HD_) * D_];
__device__ __nv_bfloat16 g_wqt_lo[(size_t)(H_ * HD_) * D_];
__device__ __nv_bfloat16 g_wkt_hi[(size_t)(KV_ * HD_) * D_];
__device__ __nv_bfloat16 g_wkt_lo[(size_t)(KV_ * HD_) * D_];
__device__ __nv_bfloat16 g_wvt_hi[(size_t)(KV_ * HD_) * D_];
__device__ __nv_bfloat16 g_wvt_lo[(size_t)(KV_ * HD_) * D_];
__device__ __nv_bfloat16 g_wot_hi[(size_t)D_ * (H_ * HD_)];
__device__ __nv_bfloat16 g_wot_lo[(size_t)D_ * (H_ * HD_)];

// ---------------------------------------------------------------------------
// PTX helpers — baseline-sm_103-safe ONLY (no tcgen05/TMEM: those are
// arch-'a' features and this harness assembles at plain sm_103; the round-7
// ptxas log proves every op below assembles).
// ---------------------------------------------------------------------------
__device__ __forceinline__ uint32_t smem_to_u32(const void* p) {
    uint32_t a;
    asm("{ .reg .u64 t; cvta.to.shared.u64 t, %1; cvt.u32.u64 %0, t; }"
        : "=r"(a) : "l"(p));
    return a;
}

// Packed fp32x2 math
__device__ __forceinline__ uint64_t ffma2(uint64_t a, uint64_t b, uint64_t c) {
    uint64_t d;
    asm("fma.rn.f32x2 %0, %1, %2, %3;" : "=l"(d) : "l"(a), "l"(b), "l"(c));
    return d;
}
__device__ __forceinline__ uint64_t fmul2(uint64_t a, uint64_t b) {
    uint64_t d;
    asm("mul.rn.f32x2 %0, %1, %2;" : "=l"(d) : "l"(a), "l"(b));
    return d;
}
__device__ __forceinline__ uint64_t pack2(float lo, float hi) {
    uint64_t d;
    asm("mov.b64 %0, {%1, %2};"
        : "=l"(d) : "r"(__float_as_uint(lo)), "r"(__float_as_uint(hi)));
    return d;
}
__device__ __forceinline__ float2 unpack2(uint64_t v) {
    uint32_t lo, hi;
    asm("mov.b64 {%0, %1}, %2;" : "=r"(lo), "=r"(hi) : "l"(v));
    return make_float2(__uint_as_float(lo), __uint_as_float(hi));
}

// cp.async 16B (Ampere+ LDGSTS)
#define CP_ASYNC16(saddr, gptr) \
    asm volatile("cp.async.cg.shared.global [%0], [%1], 16;" \
                 :: "r"((uint32_t)(saddr)), "l"(gptr) : "memory")
#define CP_ASYNC_COMMIT() \
    asm volatile("cp.async.commit_group;" ::: "memory")
#define CP_ASYNC_WAIT0() \
    asm volatile("cp.async.wait_group 0;" ::: "memory")
#define CP_ASYNC_WAIT1() \
    asm volatile("cp.async.wait_group 1;" ::: "memory")

// ldmatrix (sm_75+ baseline)
#define LDMX4(r, addr) \
    asm volatile("ldmatrix.sync.aligned.m8n8.x4.shared.b16 {%0,%1,%2,%3}, [%4];" \
                 : "=r"((r)[0]), "=r"((r)[1]), "=r"((r)[2]), "=r"((r)[3]) \
                 : "r"(addr))
#define LDMX2(r, addr) \
    asm volatile("ldmatrix.sync.aligned.m8n8.x2.shared.b16 {%0,%1}, [%2];" \
                 : "=r"((r)[0]), "=r"((r)[1]) : "r"(addr))

// mma.sync m16n8k16 bf16 -> fp32 accum (sm_80+ baseline)
__device__ __forceinline__ void mma16816(float* d, const uint32_t* a, const uint32_t* b) {
    asm volatile(
        "mma.sync.aligned.m16n8k16.row.col.f32.bf16.bf16.f32 "
        "{%0,%1,%2,%3}, {%4,%5,%6,%7}, {%8,%9}, {%0,%1,%2,%3};"
        : "+f"(d[0]), "+f"(d[1]), "+f"(d[2]), "+f"(d[3])
        : "r"(a[0]), "r"(a[1]), "r"(a[2]), "r"(a[3]), "r"(b[0]), "r"(b[1]));
}

// ---------------------------------------------------------------------------
// RoPE tables (fp64 once per launch)
// ---------------------------------------------------------------------------
__global__ void rope_table_kernel(float* __restrict__ cosT, float* __restrict__ sinT)
{
    int idx = blockIdx.x * blockDim.x + threadIdx.x;
    if (idx >= T_ * 64) return;
    int t = idx >> 6;
    int j = idx & 63;
    double inv_freq = exp(-((double)(2 * j) / (double)HD_) * log(10000.0));
    double ang = (double)t * inv_freq;
    cosT[idx] = (float)cos(ang);
    sinT[idx] = (float)sin(ang);
}

__global__ void rope_apply_kernel(float* __restrict__ x,
                                  const float* __restrict__ cosT,
                                  const float* __restrict__ sinT,
                                  int nh)
{
    int idx = blockIdx.x * blockDim.x + threadIdx.x;
    int total = M_ * nh * 64;
    if (idx >= total) return;
    int j    = idx & 63;
    int hrow = idx >> 6;
    int head = hrow % nh;
    int row  = hrow / nh;
    int t    = row & (T_ - 1);
    float c = cosT[t * 64 + j];
    float s = sinT[t * 64 + j];
    float* base = x + (size_t)row * (nh * HD_) + head * HD_ + j;
    float a = base[0];
    float b = base[64];
    base[0]  = a * c - b * s;
    base[64] = b * c + a * s;
}

// ---------------------------------------------------------------------------
// Split fp32 -> (bf16 hi, bf16 lo)
// ---------------------------------------------------------------------------
__global__ void split_kernel(const float* __restrict__ src,
                             __nv_bfloat16* __restrict__ hi,
                             __nv_bfloat16* __restrict__ lo, int n)
{
    int i = blockIdx.x * blockDim.x + threadIdx.x;
    if (i >= n) return;
    float v = src[i];
    __nv_bfloat16 h = __float2bfloat16(v);
    hi[i] = h;
    lo[i] = __float2bfloat16(v - __bfloat162float(h));
}

// Transpose + split: W[K,N] fp32 -> Wt_hi/lo[N,K] bf16. block (32,8), grid (N/32, K/32)
__global__ void transpose_split_kernel(const float* __restrict__ W,
                                       __nv_bfloat16* __restrict__ hi,
                                       __nv_bfloat16* __restrict__ lo,
                                       int K, int N)
{
    __shared__ float tile[32][33];
    int n0 = blockIdx.x * 32, k0 = blockIdx.y * 32;
    int tx = threadIdx.x, ty = threadIdx.y;
#pragma unroll
    for (int i = 0; i < 32; i += 8)
        tile[ty + i][tx] = W[(size_t)(k0 + ty + i) * N + n0 + tx];
    __syncthreads();
#pragma unroll
    for (int i = 0; i < 32; i += 8) {
        float v = tile[tx][ty + i];
        __nv_bfloat16 h = __float2bfloat16(v);
        size_t o = (size_t)(n0 + ty + i) * K + k0 + tx;
        hi[o] = h;
        lo[o] = __float2bfloat16(v - __bfloat162float(h));
    }
}

// ---------------------------------------------------------------------------
// HMMA GEMM: C[M,N] (fp32) = A @ B^T with 3-term bf16 compensation
// (hi*hi + hi*lo + lo*hi), mma.sync.m16n8k16 fragments.
// A as Ahi/Alo [M,K] bf16 row-major; B as Bhi/Blo [N,K] bf16 row-major.
// CTA tile 128x128, K chunk 32, 256 threads (8 warps in 2x4: 64x32 each),
// cp.async double-buffered smem, pitch 40 bf16 (80 B) = conflict-free ldmatrix.
// __launch_bounds__(256,2): 128-reg cap -> 2 CTAs/SM (80KB smem x2 fits 227KB);
// co-resident CTA fills our sync/wait bubbles and removes wave quantization.
// ---------------------------------------------------------------------------
#define GPITCH 40                          // bf16 elements per smem row
#define GTILEB (128 * GPITCH * 2)          // 10240 bytes per operand tile
#define GSTAGE (4 * GTILEB)                // Ahi, Alo, Bhi, Blo
#define GEMM_SMEM (2 * GSTAGE)             // 81920 bytes

__global__ __launch_bounds__(256, 2)
void mgemm_kernel(const __nv_bfloat16* __restrict__ Ahi, const __nv_bfloat16* __restrict__ Alo,
                  const __nv_bfloat16* __restrict__ Bhi, const __nv_bfloat16* __restrict__ Blo,
                  float* __restrict__ C, int Mdim, int Ndim, int Kdim)
{
    extern __shared__ __align__(16) char gsm[];
    const uint32_t sbase = smem_to_u32(gsm);
    const int tid  = threadIdx.x;
    const int wid  = tid >> 5;
    const int lane = tid & 31;
    const int bm = blockIdx.y * 128;
    const int bn = blockIdx.x * 128;
    const int wm = (wid >> 2) * 64;        // warp row offset: 0 / 64
    const int wn = (wid & 3) * 32;         // warp col offset: 0/32/64/96

    float acc[4][4][4];
#pragma unroll
    for (int mt = 0; mt < 4; mt++)
#pragma unroll
        for (int nt = 0; nt < 4; nt++)
#pragma unroll
            for (int e = 0; e < 4; e++) acc[mt][nt][e] = 0.f;

    const int nchunk = Kdim / 32;

    // --- prefetch chunk 0 ---
    {
        const uint32_t st = sbase;
#pragma unroll
        for (int p = 0; p < 2; p++) {
            int idx = tid + 256 * p;       // 0..511
            int r = idx >> 2, q = idx & 3; // row 0..127, 16B-quad 0..3
            uint32_t soff = (uint32_t)(r * 80 + q * 16);
            size_t ga = (size_t)(bm + r) * Kdim + q * 8;
            size_t gb = (size_t)(bn + r) * Kdim + q * 8;
            CP_ASYNC16(st + 0 * GTILEB + soff, Ahi + ga);
            CP_ASYNC16(st + 1 * GTILEB + soff, Alo + ga);
            CP_ASYNC16(st + 2 * GTILEB + soff, Bhi + gb);
            CP_ASYNC16(st + 3 * GTILEB + soff, Blo + gb);
        }
        CP_ASYNC_COMMIT();
    }

    // ldmatrix lane addressing (constant per thread)
    const int arow = lane & 15;                    // A: rows 0..15 within tile
    const int akq  = ((lane >> 4) & 1) * 8;        // A: k-offset 0/8
    const int brow = lane & 7;                     // B: rows 0..7 within tile
    const int bkq  = ((lane >> 3) & 1) * 8;        // B: k-offset 0/8

    for (int c = 0; c < nchunk; c++) {
        if (c + 1 < nchunk) {
            const uint32_t st = sbase + ((c + 1) & 1) * GSTAGE;
            const int kc = (c + 1) * 32;
#pragma unroll
            for (int p = 0; p < 2; p++) {
                int idx = tid + 256 * p;
                int r = idx >> 2, q = idx & 3;
                uint32_t soff = (uint32_t)(r * 80 + q * 16);
                size_t ga = (size_t)(bm + r) * Kdim + kc + q * 8;
                size_t gb = (size_t)(bn + r) * Kdim + kc + q * 8;
                CP_ASYNC16(st + 0 * GTILEB + soff, Ahi + ga);
                CP_ASYNC16(st + 1 * GTILEB + soff, Alo + ga);
                CP_ASYNC16(st + 2 * GTILEB + soff, Bhi + gb);
                CP_ASYNC16(st + 3 * GTILEB + soff, Blo + gb);
            }
            CP_ASYNC_COMMIT();
            CP_ASYNC_WAIT1();
        } else {
            CP_ASYNC_WAIT0();
        }
        __syncthreads();

        const uint32_t st = sbase + (c & 1) * GSTAGE;
#pragma unroll
        for (int ks = 0; ks < 2; ks++) {
            uint32_t ahi[4][4], alo[4][4];
#pragma unroll
            for (int mt = 0; mt < 4; mt++) {
                uint32_t ad = st + (uint32_t)(((wm + mt * 16 + arow) * GPITCH
                                               + ks * 16 + akq) * 2);
                LDMX4(ahi[mt], ad);
                LDMX4(alo[mt], ad + GTILEB);
            }
            uint32_t bhi[4][2], blo[4][2];
#pragma unroll
            for (int nt = 0; nt < 4; nt++) {
                uint32_t bd = st + 2 * GTILEB
                            + (uint32_t)(((wn + nt * 8 + brow) * GPITCH
                                          + ks * 16 + bkq) * 2);
                LDMX2(bhi[nt], bd);
                LDMX2(blo[nt], bd + GTILEB);
            }
#pragma unroll
            for (int mt = 0; mt < 4; mt++)
#pragma unroll
                for (int nt = 0; nt < 4; nt++) {
                    mma16816(acc[mt][nt], ahi[mt], bhi[nt]);
                    mma16816(acc[mt][nt], ahi[mt], blo[nt]);
                    mma16816(acc[mt][nt], alo[mt], bhi[nt]);
                }
        }
        __syncthreads();
    }

    // Epilogue: standard m16n8 fragment layout -> C (float2 vector stores;
    // col = 8*nt + 2*tig is even -> 8-byte aligned)
    const int groupID = lane >> 2;
    const int tig     = lane & 3;
#pragma unroll
    for (int mt = 0; mt < 4; mt++) {
        int row0 = bm + wm + mt * 16 + groupID;
#pragma unroll
        for (int nt = 0; nt < 4; nt++) {
            int col = bn + wn + nt * 8 + tig * 2;
            *(float2*)(C + (size_t)row0 * Ndim + col) =
                make_float2(acc[mt][nt][0], acc[mt][nt][1]);
            *(float2*)(C + (size_t)(row0 + 8) * Ndim + col) =
                make_float2(acc[mt][nt][2], acc[mt][nt][3]);
        }
    }
}

// ---------------------------------------------------------------------------
// Flash attention (causal, GQA), fp32 SIMT with packed f32x2 FMA inner loops
// and a 2-stage cp.async K/V prefetch pipeline (double-buffered smem).
// Br=Bc=64, 256 threads/CTA, online softmax, 4 rows x 8 cols per thread.
// ---------------------------------------------------------------------------
#define BR 64
#define BC 64
#define KPITCH 132   // mult of 4; 16B-aligned rows for LDS.128 / ulonglong2
#define VPITCH 132
#define SPITCH 68
#define KVBUF (BC * KPITCH)                 // floats per K (or V) buffer
#define ATTN_SMEM_FLOATS (BR*KPITCH + 2*KVBUF + 2*KVBUF + BR*SPITCH + 3*BR)
#define ATTN_SMEM_BYTES  (ATTN_SMEM_FLOATS * 4)   // 187136 B (< 227 KB cap)

__global__ __launch_bounds__(256)
void attn_kernel(const float* __restrict__ Q, const float* __restrict__ Kg,
                 const float* __restrict__ Vg, float* __restrict__ O)
{
    const int nQ  = T_ / BR;
    const int bid = blockIdx.x;
    const int bh  = bid / nQ;
    const int qi  = (nQ - 1) - (bid % nQ);   // largest q-tile first (wave balance)
    const int b   = bh / H_;
    const int h   = bh % H_;
    const int g   = h / NREP_;
    const int q0  = qi * BR;

    extern __shared__ __align__(16) float sm[];
    float* Qs  = sm;
    float* Ks0 = Qs + BR * KPITCH;           // K buffers (double)
    float* Vs0 = Ks0 + 2 * KVBUF;            // V buffers (double)
    float* Ss  = Vs0 + 2 * KVBUF;
    float* m_s = Ss + BR * SPITCH;
    float* l_s = m_s + BR;
    float* a_s = l_s + BR;

    const int tid  = threadIdx.x;
    const int tx   = tid & 15;
    const int ty   = tid >> 4;
    const int warp = tid >> 5;
    const int lane = tid & 31;

    const float scale = 0.08838834764831845f;   // 1/sqrt(128)
    const float NEG   = -1e30f;

    const uint32_t ks_u32 = smem_to_u32(Ks0);
    const uint32_t vs_u32 = smem_to_u32(Vs0);

    // Prefetch tile 0 (every CTA has at least one KV tile)
    {
#pragma unroll
        for (int p = 0; p < 8; p++) {
            int idx = tid + 256 * p;
            int r   = idx >> 5;
            int c   = (idx & 31) << 2;
            size_t goff = (size_t)(b * T_ + r) * (KV_ * HD_) + g * HD_ + c;
            uint32_t soff = (uint32_t)(r * KPITCH + c) * 4u;
            CP_ASYNC16(ks_u32 + soff, Kg + goff);
            CP_ASYNC16(vs_u32 + soff, Vg + goff);
        }
        CP_ASYNC_COMMIT();
    }

    // Q tile load, pre-multiplied by softmax scale
#pragma unroll
    for (int p = 0; p < 8; p++) {
        int idx = tid + 256 * p;
        int r   = idx >> 5;
        int c   = (idx & 31) << 2;
        float4 qv = *(const float4*)&Q[(size_t)(b * T_ + q0 + r) * (H_ * HD_) + h * HD_ + c];
        float* dst = &Qs[r * KPITCH + c];
        dst[0] = qv.x * scale; dst[1] = qv.y * scale;
        dst[2] = qv.z * scale; dst[3] = qv.w * scale;
    }
    if (tid < BR) { m_s[tid] = NEG; l_s[tid] = 0.f; }

    uint64_t o2[4][4];
#pragma unroll
    for (int i = 0; i < 4; i++)
#pragma unroll
        for (int j = 0; j < 4; j++) o2[i][j] = 0ull;

    __syncthreads();

    const int nkv = qi + 1;
    for (int kt = 0; kt < nkv; kt++) {
        if (kt + 1 < nkv) {
            const int kn = (kt + 1) * BC;
            const uint32_t boff = (uint32_t)(((kt + 1) & 1) * KVBUF) * 4u;
#pragma unroll
            for (int p = 0; p < 8; p++) {
                int idx = tid + 256 * p;
                int r   = idx >> 5;
                int c   = (idx & 31) << 2;
                size_t goff = (size_t)(b * T_ + kn + r) * (KV_ * HD_) + g * HD_ + c;
                uint32_t soff = boff + (uint32_t)(r * KPITCH + c) * 4u;
                CP_ASYNC16(ks_u32 + soff, Kg + goff);
                CP_ASYNC16(vs_u32 + soff, Vg + goff);
            }
            CP_ASYNC_COMMIT();
            CP_ASYNC_WAIT1();
        } else {
            CP_ASYNC_WAIT0();
        }
        __syncthreads();

        float* Ksb = Ks0 + (kt & 1) * KVBUF;
        float* Vsb = Vs0 + (kt & 1) * KVBUF;

        // ---- S = (scale*Q) K^T : f32x2 packed along k ----
        uint64_t accS2[4][4];
#pragma unroll
        for (int i = 0; i < 4; i++)
#pragma unroll
            for (int j = 0; j < 4; j++) accS2[i][j] = 0ull;

#pragma unroll 4
        for (int k = 0; k < HD_; k += 4) {
            ulonglong2 aq[4], bk[4];
#pragma unroll
            for (int i = 0; i < 4; i++)
                aq[i] = *(const ulonglong2*)&Qs[(ty * 4 + i) * KPITCH + k];
#pragma unroll
            for (int j = 0; j < 4; j++)
                bk[j] = *(const ulonglong2*)&Ksb[(tx + 16 * j) * KPITCH + k];
#pragma unroll
            for (int i = 0; i < 4; i++)
#pragma unroll
                for (int j = 0; j < 4; j++) {
                    accS2[i][j] = ffma2(aq[i].x, bk[j].x, accS2[i][j]);
                    accS2[i][j] = ffma2(aq[i].y, bk[j].y, accS2[i][j]);
                }
        }
        float accS[4][4];
#pragma unroll
        for (int i = 0; i < 4; i++)
#pragma unroll
            for (int j = 0; j < 4; j++) {
                float2 t = unpack2(accS2[i][j]);
                accS[i][j] = t.x + t.y;
            }

        if (kt == qi) {
#pragma unroll
            for (int i = 0; i < 4; i++) {
                int r = ty * 4 + i;
#pragma unroll
                for (int j = 0; j < 4; j++) {
                    int c = tx + 16 * j;
                    Ss[r * SPITCH + c] = (c <= r) ? accS[i][j] : NEG;
                }
            }
        } else {
#pragma unroll
            for (int i = 0; i < 4; i++)
#pragma unroll
                for (int j = 0; j < 4; j++)
                    Ss[(ty * 4 + i) * SPITCH + tx + 16 * j] = accS[i][j];
        }
        __syncthreads();

        // ---- online softmax ----
        for (int rl = 0; rl < 8; rl++) {
            int r = warp * 8 + rl;
            float x0 = Ss[r * SPITCH + lane];
            float x1 = Ss[r * SPITCH + lane + 32];
            float mx = fmaxf(x0, x1);
#pragma unroll
            for (int off = 16; off; off >>= 1)
                mx = fmaxf(mx, __shfl_xor_sync(0xffffffffu, mx, off));
            float mold = m_s[r];
            float mnew = fmaxf(mold, mx);
            float e0 = __expf(x0 - mnew);
            float e1 = __expf(x1 - mnew);
            Ss[r * SPITCH + lane]      = e0;
            Ss[r * SPITCH + lane + 32] = e1;
            float sum = e0 + e1;
#pragma unroll
            for (int off = 16; off; off >>= 1)
                sum += __shfl_xor_sync(0xffffffffu, sum, off);
            if (lane == 0) {
                float alpha = __expf(mold - mnew);
                l_s[r] = l_s[r] * alpha + sum;
                m_s[r] = mnew;
                a_s[r] = alpha;
            }
        }
        __syncthreads();

        // ---- O = alpha*O + P V : f32x2 packed along output columns ----
#pragma unroll
        for (int i = 0; i < 4; i++) {
            uint64_t alpha2 = pack2(a_s[ty * 4 + i], a_s[ty * 4 + i]);
#pragma unroll
            for (int j = 0; j < 4; j++) o2[i][j] = fmul2(o2[i][j], alpha2);
        }
#pragma unroll 2
        for (int s = 0; s < BC; s += 4) {
            float4 p4[4];
#pragma unroll
            for (int i = 0; i < 4; i++)
                p4[i] = *(const float4*)&Ss[(ty * 4 + i) * SPITCH + s];
#pragma unroll
            for (int ss = 0; ss < 4; ss++) {
                ulonglong2 v0 = *(const ulonglong2*)&Vsb[(s + ss) * VPITCH + tx * 8];
                ulonglong2 v1 = *(const ulonglong2*)&Vsb[(s + ss) * VPITCH + tx * 8 + 4];
#pragma unroll
                for (int i = 0; i < 4; i++) {
                    float p = (ss == 0) ? p4[i].x : (ss == 1) ? p4[i].y
                             : (ss == 2) ? p4[i].z : p4[i].w;
                    uint64_t pp = pack2(p, p);
                    o2[i][0] = ffma2(pp, v0.x, o2[i][0]);
                    o2[i][1] = ffma2(pp, v0.y, o2[i][1]);
                    o2[i][2] = ffma2(pp, v1.x, o2[i][2]);
                    o2[i][3] = ffma2(pp, v1.y, o2[i][3]);
                }
            }
        }
        __syncthreads();
    }

    // Epilogue: unpack, normalize, store
#pragma unroll
    for (int i = 0; i < 4; i++) {
        int r = ty * 4 + i;
        float inv = 1.0f / l_s[r];
        float2 t0 = unpack2(o2[i][0]);
        float2 t1 = unpack2(o2[i][1]);
        float2 t2 = unpack2(o2[i][2]);
        float2 t3 = unpack2(o2[i][3]);
        float* op = &O[(size_t)(b * T_ + q0 + r) * (H_ * HD_) + h * HD_ + tx * 8];
        *(float4*)op       = make_float4(t0.x * inv, t0.y * inv, t1.x * inv, t1.y * inv);
        *(float4*)(op + 4) = make_float4(t2.x * inv, t2.y * inv, t3.x * inv, t3.y * inv);
    }
}

// ---------------------------------------------------------------------------
// Host orchestration (graph-capturable: kernel launches only)
// ---------------------------------------------------------------------------
extern "C" void kernel_launch(void* const* d_in, const int* in_sizes, int n_in,
                              void* d_out, int out_size)
{
    const float* x  = (const float*)d_in[0];
    const float* Wq = (const float*)d_in[1];
    const float* Wk = (const float*)d_in[2];
    const float* Wv = (const float*)d_in[3];
    const float* Wo = (const float*)d_in[4];
    float* out = (float*)d_out;

    float *q, *k, *v, *ao, *ct, *st;
    cudaGetSymbolAddress((void**)&q,  g_q);
    cudaGetSymbolAddress((void**)&k,  g_k);
    cudaGetSymbolAddress((void**)&v,  g_v);
    cudaGetSymbolAddress((void**)&ao, g_ao);
    cudaGetSymbolAddress((void**)&ct, g_cos);
    cudaGetSymbolAddress((void**)&st, g_sin);

    __nv_bfloat16 *xhi, *xlo, *aohi, *aolo;
    __nv_bfloat16 *wqh, *wql, *wkh, *wkl, *wvh, *wvl, *woh, *wol;
    cudaGetSymbolAddress((void**)&xhi,  g_xhi);
    cudaGetSymbolAddress((void**)&xlo,  g_xlo);
    cudaGetSymbolAddress((void**)&aohi, g_aohi);
    cudaGetSymbolAddress((void**)&aolo, g_aolo);
    cudaGetSymbolAddress((void**)&wqh,  g_wqt_hi);
    cudaGetSymbolAddress((void**)&wql,  g_wqt_lo);
    cudaGetSymbolAddress((void**)&wkh,  g_wkt_hi);
    cudaGetSymbolAddress((void**)&wkl,  g_wkt_lo);
    cudaGetSymbolAddress((void**)&wvh,  g_wvt_hi);
    cudaGetSymbolAddress((void**)&wvl,  g_wvt_lo);
    cudaGetSymbolAddress((void**)&woh,  g_wot_hi);
    cudaGetSymbolAddress((void**)&wol,  g_wot_lo);

    cudaFuncSetAttribute(attn_kernel, cudaFuncAttributeMaxDynamicSharedMemorySize,
                         ATTN_SMEM_BYTES);
    cudaFuncSetAttribute(mgemm_kernel, cudaFuncAttributeMaxDynamicSharedMemorySize,
                         GEMM_SMEM);

    // ---- precompute: RoPE tables, operand splits, weight transposes ----
    rope_table_kernel<<<(T_ * 64 + 255) / 256, 256>>>(ct, st);

    const int nx = M_ * D_;
    split_kernel<<<(nx + 255) / 256, 256>>>(x, xhi, xlo, nx);

    dim3 tsb(32, 8);
    transpose_split_kernel<<<dim3((H_ * HD_) / 32,  D_ / 32), tsb>>>(Wq, wqh, wql, D_, H_ * HD_);
    transpose_split_kernel<<<dim3((KV_ * HD_) / 32, D_ / 32), tsb>>>(Wk, wkh, wkl, D_, KV_ * HD_);
    transpose_split_kernel<<<dim3((KV_ * HD_) / 32, D_ / 32), tsb>>>(Wv, wvh, wvl, D_, KV_ * HD_);
    transpose_split_kernel<<<dim3(D_ / 32, (H_ * HD_) / 32), tsb>>>(Wo, woh, wol, H_ * HD_, D_);

    // ---- QKV projections (HMMA) ----
    mgemm_kernel<<<dim3((H_ * HD_) / 128,  M_ / 128), 256, GEMM_SMEM>>>(
        xhi, xlo, wqh, wql, q, M_, H_ * HD_, D_);
    mgemm_kernel<<<dim3((KV_ * HD_) / 128, M_ / 128), 256, GEMM_SMEM>>>(
        xhi, xlo, wkh, wkl, k, M_, KV_ * HD_, D_);
    mgemm_kernel<<<dim3((KV_ * HD_) / 128, M_ / 128), 256, GEMM_SMEM>>>(
        xhi, xlo, wvh, wvl, v, M_, KV_ * HD_, D_);

    // ---- RoPE ----
    rope_apply_kernel<<<(M_ * H_  * 64) / 256, 256>>>(q, ct, st, H_);
    rope_apply_kernel<<<(M_ * KV_ * 64) / 256, 256>>>(k, ct, st, KV_);

    // ---- causal GQA flash attention (fp32 SIMT + f32x2 + cp.async pipeline) ----
    attn_kernel<<<(T_ / BR) * B_ * H_, 256, ATTN_SMEM_BYTES>>>(q, k, v, ao);

    // ---- output projection (HMMA) ----
    split_kernel<<<(nx + 255) / 256, 256>>>(ao, aohi, aolo, nx);
    mgemm_kernel<<<dim3(D_ / 128, M_ / 128), 256, GEMM_SMEM>>>(
        aohi, aolo, woh, wol, out, M_, D_, H_ * HD_);
}

// round 13
// speedup vs baseline: 1.4867x; 1.4867x over previous
#include <cuda_runtime.h>
#include <cuda_bf16.h>
#include <math.h>
#include <stdint.h>

// ---------------------------------------------------------------------------
// Problem constants
// ---------------------------------------------------------------------------
#define B_    2
#define T_    2048
#define D_    2048
#define H_    16
#define KV_   4
#define HD_   128
#define NREP_ 4
#define M_    (B_ * T_)          // 4096 rows

// ---------------------------------------------------------------------------
// Static device scratch (no cudaMalloc allowed)
// ---------------------------------------------------------------------------
__device__ float g_q [(size_t)M_ * (H_ * HD_)];
__device__ float g_k [(size_t)M_ * (KV_ * HD_)];
__device__ float g_v [(size_t)M_ * (KV_ * HD_)];
__device__ float g_ao[(size_t)M_ * (H_ * HD_)];
__device__ float g_cos[T_ * 64];
__device__ float g_sin[T_ * 64];

// bf16 split operands (hi + lo decomposition for compensated MMA)
__device__ __nv_bfloat16 g_xhi [(size_t)M_ * D_];
__device__ __nv_bfloat16 g_xlo [(size_t)M_ * D_];
__device__ __nv_bfloat16 g_aohi[(size_t)M_ * D_];
__device__ __nv_bfloat16 g_aolo[(size_t)M_ * D_];
__device__ __nv_bfloat16 g_wqt_hi[(size_t)(H_ * HD_) * D_];
__device__ __nv_bfloat16 g_wqt_lo[(size_t)(H_ * HD_) * D_];
__device__ __nv_bfloat16 g_wkt_hi[(size_t)(KV_ * HD_) * D_];
__device__ __nv_bfloat16 g_wkt_lo[(size_t)(KV_ * HD_) * D_];
__device__ __nv_bfloat16 g_wvt_hi[(size_t)(KV_ * HD_) * D_];
__device__ __nv_bfloat16 g_wvt_lo[(size_t)(KV_ * HD_) * D_];
__device__ __nv_bfloat16 g_wot_hi[(size_t)D_ * (H_ * HD_)];
__device__ __nv_bfloat16 g_wot_lo[(size_t)D_ * (H_ * HD_)];
// attention operands: Q/K split after RoPE; V transposed per head [hd][t] + split
__device__ __nv_bfloat16 g_qhi[(size_t)M_ * (H_ * HD_)];
__device__ __nv_bfloat16 g_qlo[(size_t)M_ * (H_ * HD_)];
__device__ __nv_bfloat16 g_khi[(size_t)M_ * (KV_ * HD_)];
__device__ __nv_bfloat16 g_klo[(size_t)M_ * (KV_ * HD_)];
__device__ __nv_bfloat16 g_vthi[(size_t)B_ * KV_ * HD_ * T_];
__device__ __nv_bfloat16 g_vtlo[(size_t)B_ * KV_ * HD_ * T_];

// ---------------------------------------------------------------------------
// PTX helpers — baseline-sm_103-safe (all HW-validated in round 11's pass)
// ---------------------------------------------------------------------------
__device__ __forceinline__ uint32_t smem_to_u32(const void* p) {
    uint32_t a;
    asm("{ .reg .u64 t; cvta.to.shared.u64 t, %1; cvt.u32.u64 %0, t; }"
        : "=r"(a) : "l"(p));
    return a;
}

#define CP_ASYNC16(saddr, gptr) \
    asm volatile("cp.async.cg.shared.global [%0], [%1], 16;" \
                 :: "r"((uint32_t)(saddr)), "l"(gptr) : "memory")
#define CP_ASYNC_COMMIT() \
    asm volatile("cp.async.commit_group;" ::: "memory")
#define CP_ASYNC_WAIT0() \
    asm volatile("cp.async.wait_group 0;" ::: "memory")
#define CP_ASYNC_WAIT1() \
    asm volatile("cp.async.wait_group 1;" ::: "memory")

#define LDMX4(r, addr) \
    asm volatile("ldmatrix.sync.aligned.m8n8.x4.shared.b16 {%0,%1,%2,%3}, [%4];" \
                 : "=r"((r)[0]), "=r"((r)[1]), "=r"((r)[2]), "=r"((r)[3]) \
                 : "r"(addr))
#define LDMX2(r, addr) \
    asm volatile("ldmatrix.sync.aligned.m8n8.x2.shared.b16 {%0,%1}, [%2];" \
                 : "=r"((r)[0]), "=r"((r)[1]) : "r"(addr))

__device__ __forceinline__ void mma16816(float* d, const uint32_t* a, const uint32_t* b) {
    asm volatile(
        "mma.sync.aligned.m16n8k16.row.col.f32.bf16.bf16.f32 "
        "{%0,%1,%2,%3}, {%4,%5,%6,%7}, {%8,%9}, {%0,%1,%2,%3};"
        : "+f"(d[0]), "+f"(d[1]), "+f"(d[2]), "+f"(d[3])
        : "r"(a[0]), "r"(a[1]), "r"(a[2]), "r"(a[3]), "r"(b[0]), "r"(b[1]));
}

// ---------------------------------------------------------------------------
// RoPE tables
// ---------------------------------------------------------------------------
__global__ void rope_table_kernel(float* __restrict__ cosT, float* __restrict__ sinT)
{
    int idx = blockIdx.x * blockDim.x + threadIdx.x;
    if (idx >= T_ * 64) return;
    int t = idx >> 6;
    int j = idx & 63;
    double inv_freq = exp(-((double)(2 * j) / (double)HD_) * log(10000.0));
    double ang = (double)t * inv_freq;
    cosT[idx] = (float)cos(ang);
    sinT[idx] = (float)sin(ang);
}

__global__ void rope_apply_kernel(float* __restrict__ x,
                                  const float* __restrict__ cosT,
                                  const float* __restrict__ sinT,
                                  int nh)
{
    int idx = blockIdx.x * blockDim.x + threadIdx.x;
    int total = M_ * nh * 64;
    if (idx >= total) return;
    int j    = idx & 63;
    int hrow = idx >> 6;
    int head = hrow % nh;
    int row  = hrow / nh;
    int t    = row & (T_ - 1);
    float c = cosT[t * 64 + j];
    float s = sinT[t * 64 + j];
    float* base = x + (size_t)row * (nh * HD_) + head * HD_ + j;
    float a = base[0];
    float b = base[64];
    base[0]  = a * c - b * s;
    base[64] = b * c + a * s;
}

// ---------------------------------------------------------------------------
// Split fp32 -> (bf16 hi, bf16 lo), with optional pre-scale
// ---------------------------------------------------------------------------
__global__ void split_kernel(const float* __restrict__ src,
                             __nv_bfloat16* __restrict__ hi,
                             __nv_bfloat16* __restrict__ lo, int n, float scale)
{
    int i = blockIdx.x * blockDim.x + threadIdx.x;
    if (i >= n) return;
    float v = src[i] * scale;
    __nv_bfloat16 h = __float2bfloat16(v);
    hi[i] = h;
    lo[i] = __float2bfloat16(v - __bfloat162float(h));
}

// Transpose + split: W[K,N] fp32 -> Wt_hi/lo[N,K] bf16.
__global__ void transpose_split_kernel(const float* __restrict__ W,
                                       __nv_bfloat16* __restrict__ hi,
                                       __nv_bfloat16* __restrict__ lo,
                                       int K, int N)
{
    __shared__ float tile[32][33];
    int n0 = blockIdx.x * 32, k0 = blockIdx.y * 32;
    int tx = threadIdx.x, ty = threadIdx.y;
#pragma unroll
    for (int i = 0; i < 32; i += 8)
        tile[ty + i][tx] = W[(size_t)(k0 + ty + i) * N + n0 + tx];
    __syncthreads();
#pragma unroll
    for (int i = 0; i < 32; i += 8) {
        float v = tile[tx][ty + i];
        __nv_bfloat16 h = __float2bfloat16(v);
        size_t o = (size_t)(n0 + ty + i) * K + k0 + tx;
        hi[o] = h;
        lo[o] = __float2bfloat16(v - __bfloat162float(h));
    }
}

// V transpose+split per head: g_v [b*T+t][g*HD+hd] fp32 -> out[(b,g,hd)][t] bf16 hi/lo
// grid (T/32, HD/32, B*KV), block (32,8)
__global__ void vtrans_split_kernel(const float* __restrict__ V,
                                    __nv_bfloat16* __restrict__ hi,
                                    __nv_bfloat16* __restrict__ lo)
{
    __shared__ float tile[32][33];
    int t0 = blockIdx.x * 32, d0 = blockIdx.y * 32;
    int bg = blockIdx.z;
    int b = bg / KV_, g = bg % KV_;
    int tx = threadIdx.x, ty = threadIdx.y;
#pragma unroll
    for (int i = 0; i < 32; i += 8)
        tile[ty + i][tx] = V[(size_t)(b * T_ + t0 + ty + i) * (KV_ * HD_) + g * HD_ + d0 + tx];
    __syncthreads();
#pragma unroll
    for (int i = 0; i < 32; i += 8) {
        float v = tile[tx][ty + i];   // value at t = t0+tx, hd = d0+ty+i
        __nv_bfloat16 h = __float2bfloat16(v);
        size_t o = ((size_t)bg * HD_ + d0 + ty + i) * T_ + t0 + tx;
        hi[o] = h;
        lo[o] = __float2bfloat16(v - __bfloat162float(h));
    }
}

// ---------------------------------------------------------------------------
// HMMA GEMM (unchanged from the 2311us passing version)
// ---------------------------------------------------------------------------
#define GPITCH 40
#define GTILEB (128 * GPITCH * 2)
#define GSTAGE (4 * GTILEB)
#define GEMM_SMEM (2 * GSTAGE)             // 81920 bytes

__global__ __launch_bounds__(256, 2)
void mgemm_kernel(const __nv_bfloat16* __restrict__ Ahi, const __nv_bfloat16* __restrict__ Alo,
                  const __nv_bfloat16* __restrict__ Bhi, const __nv_bfloat16* __restrict__ Blo,
                  float* __restrict__ C, int Mdim, int Ndim, int Kdim)
{
    extern __shared__ __align__(16) char gsm[];
    const uint32_t sbase = smem_to_u32(gsm);
    const int tid  = threadIdx.x;
    const int wid  = tid >> 5;
    const int lane = tid & 31;
    const int bm = blockIdx.y * 128;
    const int bn = blockIdx.x * 128;
    const int wm = (wid >> 2) * 64;
    const int wn = (wid & 3) * 32;

    float acc[4][4][4];
#pragma unroll
    for (int mt = 0; mt < 4; mt++)
#pragma unroll
        for (int nt = 0; nt < 4; nt++)
#pragma unroll
            for (int e = 0; e < 4; e++) acc[mt][nt][e] = 0.f;

    const int nchunk = Kdim / 32;
    {
        const uint32_t st = sbase;
#pragma unroll
        for (int p = 0; p < 2; p++) {
            int idx = tid + 256 * p;
            int r = idx >> 2, q = idx & 3;
            uint32_t soff = (uint32_t)(r * 80 + q * 16);
            size_t ga = (size_t)(bm + r) * Kdim + q * 8;
            size_t gb = (size_t)(bn + r) * Kdim + q * 8;
            CP_ASYNC16(st + 0 * GTILEB + soff, Ahi + ga);
            CP_ASYNC16(st + 1 * GTILEB + soff, Alo + ga);
            CP_ASYNC16(st + 2 * GTILEB + soff, Bhi + gb);
            CP_ASYNC16(st + 3 * GTILEB + soff, Blo + gb);
        }
        CP_ASYNC_COMMIT();
    }

    const int arow = lane & 15;
    const int akq  = ((lane >> 4) & 1) * 8;
    const int brow = lane & 7;
    const int bkq  = ((lane >> 3) & 1) * 8;

    for (int c = 0; c < nchunk; c++) {
        if (c + 1 < nchunk) {
            const uint32_t st = sbase + ((c + 1) & 1) * GSTAGE;
            const int kc = (c + 1) * 32;
#pragma unroll
            for (int p = 0; p < 2; p++) {
                int idx = tid + 256 * p;
                int r = idx >> 2, q = idx & 3;
                uint32_t soff = (uint32_t)(r * 80 + q * 16);
                size_t ga = (size_t)(bm + r) * Kdim + kc + q * 8;
                size_t gb = (size_t)(bn + r) * Kdim + kc + q * 8;
                CP_ASYNC16(st + 0 * GTILEB + soff, Ahi + ga);
                CP_ASYNC16(st + 1 * GTILEB + soff, Alo + ga);
                CP_ASYNC16(st + 2 * GTILEB + soff, Bhi + gb);
                CP_ASYNC16(st + 3 * GTILEB + soff, Blo + gb);
            }
            CP_ASYNC_COMMIT();
            CP_ASYNC_WAIT1();
        } else {
            CP_ASYNC_WAIT0();
        }
        __syncthreads();

        const uint32_t st = sbase + (c & 1) * GSTAGE;
#pragma unroll
        for (int ks = 0; ks < 2; ks++) {
            uint32_t ahi[4][4], alo[4][4];
#pragma unroll
            for (int mt = 0; mt < 4; mt++) {
                uint32_t ad = st + (uint32_t)(((wm + mt * 16 + arow) * GPITCH
                                               + ks * 16 + akq) * 2);
                LDMX4(ahi[mt], ad);
                LDMX4(alo[mt], ad + GTILEB);
            }
            uint32_t bhi[4][2], blo[4][2];
#pragma unroll
            for (int nt = 0; nt < 4; nt++) {
                uint32_t bd = st + 2 * GTILEB
                            + (uint32_t)(((wn + nt * 8 + brow) * GPITCH
                                          + ks * 16 + bkq) * 2);
                LDMX2(bhi[nt], bd);
                LDMX2(blo[nt], bd + GTILEB);
            }
#pragma unroll
            for (int mt = 0; mt < 4; mt++)
#pragma unroll
                for (int nt = 0; nt < 4; nt++) {
                    mma16816(acc[mt][nt], ahi[mt], bhi[nt]);
                    mma16816(acc[mt][nt], ahi[mt], blo[nt]);
                    mma16816(acc[mt][nt], alo[mt], bhi[nt]);
                }
        }
        __syncthreads();
    }

    const int groupID = lane >> 2;
    const int tig     = lane & 3;
#pragma unroll
    for (int mt = 0; mt < 4; mt++) {
        int row0 = bm + wm + mt * 16 + groupID;
#pragma unroll
        for (int nt = 0; nt < 4; nt++) {
            int col = bn + wn + nt * 8 + tig * 2;
            *(float2*)(C + (size_t)row0 * Ndim + col) =
                make_float2(acc[mt][nt][0], acc[mt][nt][1]);
            *(float2*)(C + (size_t)(row0 + 8) * Ndim + col) =
                make_float2(acc[mt][nt][2], acc[mt][nt][3]);
        }
    }
}

// ---------------------------------------------------------------------------
// HMMA flash attention (causal, GQA). Br=Bc=64, 256 threads (8 warps).
// S = (scaled Q)K^T and O += P V both on mma.sync.m16n8k16 with 3-term
// hi/lo compensation. V consumed pre-transposed per head ([hd][t]) so the
// B-operand uses the identical (HW-validated) [N][K] LDMX2 pattern.
// Q/K pitch 136 bf16 (272B = 16*17: conflict-free), P/VT pitch 72 (144B=16*9).
// ---------------------------------------------------------------------------
#define AQP 136
#define AVP 72
#define ASP 68
#define A_QHI 0
#define A_QLO 17408
#define A_K(buf, part) (34816 + ((buf) * 2 + (part)) * 17408)
#define A_VT(buf, part) (104448 + ((buf) * 2 + (part)) * 18432)
#define A_SS  178176
#define A_PHI 195584
#define A_PLO 204800
#define A_M   214016
#define A_L   214272
#define A_A   214528
#define ATTN_SMEM 214784

__global__ __launch_bounds__(256)
void attn_hmma_kernel(const __nv_bfloat16* __restrict__ Qhi, const __nv_bfloat16* __restrict__ Qlo,
                      const __nv_bfloat16* __restrict__ Khi, const __nv_bfloat16* __restrict__ Klo,
                      const __nv_bfloat16* __restrict__ VThi, const __nv_bfloat16* __restrict__ VTlo,
                      float* __restrict__ O)
{
    const int nQ  = T_ / 64;
    const int bid = blockIdx.x;
    const int bh  = bid / nQ;
    const int qi  = (nQ - 1) - (bid % nQ);
    const int b   = bh / H_;
    const int h   = bh % H_;
    const int g   = h / NREP_;
    const int q0  = qi * 64;
    const int bg  = b * KV_ + g;

    extern __shared__ __align__(16) char asmem[];
    const uint32_t sb = smem_to_u32(asmem);
    float* Ss  = (float*)(asmem + A_SS);
    float* m_s = (float*)(asmem + A_M);
    float* l_s = (float*)(asmem + A_L);
    float* a_s = (float*)(asmem + A_A);
    __nv_bfloat16* Phi = (__nv_bfloat16*)(asmem + A_PHI);
    __nv_bfloat16* Plo = (__nv_bfloat16*)(asmem + A_PLO);

    const int tid  = threadIdx.x;
    const int w    = tid >> 5;
    const int lane = tid & 31;
    const int groupID = lane >> 2;
    const int tig     = lane & 3;
    const int arow = lane & 15, akq = ((lane >> 4) & 1) * 8;
    const int brow = lane & 7,  bkq = ((lane >> 3) & 1) * 8;
    const float NEG = -1e30f;

    // ---- prefetch Q + tile 0 (one cp.async group) ----
    {
#pragma unroll
        for (int p = 0; p < 4; p++) {
            int it = tid + 256 * p;
            int r = it >> 4, q = it & 15;
            size_t src = (size_t)(b * T_ + q0 + r) * (H_ * HD_) + h * HD_ + q * 8;
            CP_ASYNC16(sb + A_QHI + r * 272 + q * 16, Qhi + src);
            CP_ASYNC16(sb + A_QLO + r * 272 + q * 16, Qlo + src);
        }
#pragma unroll
        for (int p = 0; p < 4; p++) {
            int it = tid + 256 * p;
            int r = it >> 4, q = it & 15;
            size_t src = (size_t)(b * T_ + r) * (KV_ * HD_) + g * HD_ + q * 8;
            CP_ASYNC16(sb + A_K(0, 0) + r * 272 + q * 16, Khi + src);
            CP_ASYNC16(sb + A_K(0, 1) + r * 272 + q * 16, Klo + src);
        }
#pragma unroll
        for (int p = 0; p < 4; p++) {
            int it = tid + 256 * p;
            int r = it >> 3, q = it & 7;
            size_t src = ((size_t)bg * HD_ + r) * T_ + q * 8;
            CP_ASYNC16(sb + A_VT(0, 0) + r * 144 + q * 16, VThi + src);
            CP_ASYNC16(sb + A_VT(0, 1) + r * 144 + q * 16, VTlo + src);
        }
        CP_ASYNC_COMMIT();
    }
    if (tid < 64) { m_s[tid] = NEG; l_s[tid] = 0.f; }

    float oacc[2][4][4];
#pragma unroll
    for (int mt = 0; mt < 2; mt++)
#pragma unroll
        for (int nt = 0; nt < 4; nt++)
#pragma unroll
            for (int e = 0; e < 4; e++) oacc[mt][nt][e] = 0.f;

    const int wm2 = (w >> 2) * 32;       // rows for S and PV
    const int wn2 = (w & 3) * 16;        // S cols (kv)
    const int wnO = (w & 3) * 32;        // PV cols (hd)

    const int nkv = qi + 1;
    for (int kt = 0; kt < nkv; kt++) {
        if (kt + 1 < nkv) {
            const int bufn = (kt + 1) & 1;
            const int k0n = (kt + 1) * 64;
#pragma unroll
            for (int p = 0; p < 4; p++) {
                int it = tid + 256 * p;
                int r = it >> 4, q = it & 15;
                size_t src = (size_t)(b * T_ + k0n + r) * (KV_ * HD_) + g * HD_ + q * 8;
                CP_ASYNC16(sb + A_K(bufn, 0) + r * 272 + q * 16, Khi + src);
                CP_ASYNC16(sb + A_K(bufn, 1) + r * 272 + q * 16, Klo + src);
            }
#pragma unroll
            for (int p = 0; p < 4; p++) {
                int it = tid + 256 * p;
                int r = it >> 3, q = it & 7;
                size_t src = ((size_t)bg * HD_ + r) * T_ + k0n + q * 8;
                CP_ASYNC16(sb + A_VT(bufn, 0) + r * 144 + q * 16, VThi + src);
                CP_ASYNC16(sb + A_VT(bufn, 1) + r * 144 + q * 16, VTlo + src);
            }
            CP_ASYNC_COMMIT();
            CP_ASYNC_WAIT1();
        } else {
            CP_ASYNC_WAIT0();
        }
        __syncthreads();

        const uint32_t kb = sb + A_K(kt & 1, 0);    // hi; lo at +17408
        const uint32_t vb = sb + A_VT(kt & 1, 0);   // hi; lo at +18432

        // ---- S = Q K^T (3-term) ----
        float sacc[2][2][4];
#pragma unroll
        for (int mt = 0; mt < 2; mt++)
#pragma unroll
            for (int nt = 0; nt < 2; nt++)
#pragma unroll
                for (int e = 0; e < 4; e++) sacc[mt][nt][e] = 0.f;

#pragma unroll
        for (int ks = 0; ks < 8; ks++) {
            uint32_t qh[2][4], ql[2][4];
#pragma unroll
            for (int mt = 0; mt < 2; mt++) {
                uint32_t ad = sb + A_QHI
                    + (uint32_t)(((wm2 + mt * 16 + arow) * AQP + ks * 16 + akq) * 2);
                LDMX4(qh[mt], ad);
                LDMX4(ql[mt], ad + (A_QLO - A_QHI));
            }
            uint32_t kh[2][2], kl[2][2];
#pragma unroll
            for (int nt = 0; nt < 2; nt++) {
                uint32_t bd = kb
                    + (uint32_t)(((wn2 + nt * 8 + brow) * AQP + ks * 16 + bkq) * 2);
                LDMX2(kh[nt], bd);
                LDMX2(kl[nt], bd + 17408);
            }
#pragma unroll
            for (int mt = 0; mt < 2; mt++)
#pragma unroll
                for (int nt = 0; nt < 2; nt++) {
                    mma16816(sacc[mt][nt], qh[mt], kh[nt]);
                    mma16816(sacc[mt][nt], qh[mt], kl[nt]);
                    mma16816(sacc[mt][nt], ql[mt], kh[nt]);
                }
        }

        // ---- causal mask (diagonal tile only) + store to Ss ----
#pragma unroll
        for (int mt = 0; mt < 2; mt++) {
            int r0 = wm2 + mt * 16 + groupID;
#pragma unroll
            for (int nt = 0; nt < 2; nt++) {
                int c = wn2 + nt * 8 + tig * 2;
                float v0 = sacc[mt][nt][0], v1 = sacc[mt][nt][1];
                float v2 = sacc[mt][nt][2], v3 = sacc[mt][nt][3];
                if (kt == qi) {
                    if (c     > r0)     v0 = NEG;
                    if (c + 1 > r0)     v1 = NEG;
                    if (c     > r0 + 8) v2 = NEG;
                    if (c + 1 > r0 + 8) v3 = NEG;
                }
                Ss[r0 * ASP + c]           = v0;
                Ss[r0 * ASP + c + 1]       = v1;
                Ss[(r0 + 8) * ASP + c]     = v2;
                Ss[(r0 + 8) * ASP + c + 1] = v3;
            }
        }
        __syncthreads();

        // ---- online softmax; emit P as bf16 hi/lo ----
        for (int rl = 0; rl < 8; rl++) {
            int r = w * 8 + rl;
            float x0 = Ss[r * ASP + lane];
            float x1 = Ss[r * ASP + lane + 32];
            float mx = fmaxf(x0, x1);
#pragma unroll
            for (int off = 16; off; off >>= 1)
                mx = fmaxf(mx, __shfl_xor_sync(0xffffffffu, mx, off));
            float mold = m_s[r];
            float mnew = fmaxf(mold, mx);
            float e0 = __expf(x0 - mnew);
            float e1 = __expf(x1 - mnew);
            __nv_bfloat16 h0 = __float2bfloat16(e0);
            __nv_bfloat16 h1 = __float2bfloat16(e1);
            Phi[r * AVP + lane]      = h0;
            Plo[r * AVP + lane]      = __float2bfloat16(e0 - __bfloat162float(h0));
            Phi[r * AVP + lane + 32] = h1;
            Plo[r * AVP + lane + 32] = __float2bfloat16(e1 - __bfloat162float(h1));
            float sum = e0 + e1;
#pragma unroll
            for (int off = 16; off; off >>= 1)
                sum += __shfl_xor_sync(0xffffffffu, sum, off);
            if (lane == 0) {
                float alpha = __expf(mold - mnew);
                l_s[r] = l_s[r] * alpha + sum;
                m_s[r] = mnew;
                a_s[r] = alpha;
            }
        }
        __syncthreads();

        // ---- O = alpha*O + P V (3-term) ----
#pragma unroll
        for (int mt = 0; mt < 2; mt++) {
            float a0 = a_s[wm2 + mt * 16 + groupID];
            float a1 = a_s[wm2 + mt * 16 + groupID + 8];
#pragma unroll
            for (int nt = 0; nt < 4; nt++) {
                oacc[mt][nt][0] *= a0; oacc[mt][nt][1] *= a0;
                oacc[mt][nt][2] *= a1; oacc[mt][nt][3] *= a1;
            }
        }
#pragma unroll
        for (int ks = 0; ks < 4; ks++) {
            uint32_t ph[2][4], pl[2][4];
#pragma unroll
            for (int mt = 0; mt < 2; mt++) {
                uint32_t ad = sb + A_PHI
                    + (uint32_t)(((wm2 + mt * 16 + arow) * AVP + ks * 16 + akq) * 2);
                LDMX4(ph[mt], ad);
                LDMX4(pl[mt], ad + (A_PLO - A_PHI));
            }
            uint32_t vh[4][2], vl[4][2];
#pragma unroll
            for (int nt = 0; nt < 4; nt++) {
                uint32_t bd = vb
                    + (uint32_t)(((wnO + nt * 8 + brow) * AVP + ks * 16 + bkq) * 2);
                LDMX2(vh[nt], bd);
                LDMX2(vl[nt], bd + 18432);
            }
#pragma unroll
            for (int mt = 0; mt < 2; mt++)
#pragma unroll
                for (int nt = 0; nt < 4; nt++) {
                    mma16816(oacc[mt][nt], ph[mt], vh[nt]);
                    mma16816(oacc[mt][nt], ph[mt], vl[nt]);
                    mma16816(oacc[mt][nt], pl[mt], vh[nt]);
                }
        }
        __syncthreads();   // buffer-release barrier for next prefetch
    }

    // ---- epilogue: normalize, store ----
#pragma unroll
    for (int mt = 0; mt < 2; mt++) {
        int rl0 = wm2 + mt * 16 + groupID;
        float inv0 = 1.0f / l_s[rl0];
        float inv1 = 1.0f / l_s[rl0 + 8];
#pragma unroll
        for (int nt = 0; nt < 4; nt++) {
            int c = wnO + nt * 8 + tig * 2;
            float* op = O + (size_t)(b * T_ + q0 + rl0) * (H_ * HD_) + h * HD_ + c;
            *(float2*)op = make_float2(oacc[mt][nt][0] * inv0, oacc[mt][nt][1] * inv0);
            *(float2*)(op + (size_t)8 * (H_ * HD_)) =
                make_float2(oacc[mt][nt][2] * inv1, oacc[mt][nt][3] * inv1);
        }
    }
}

// ---------------------------------------------------------------------------
// Host orchestration (graph-capturable: kernel launches only)
// Launch order puts mgemm(Q) at launch #6 so ncu (-s 5 -c 1) profiles it.
// ---------------------------------------------------------------------------
extern "C" void kernel_launch(void* const* d_in, const int* in_sizes, int n_in,
                              void* d_out, int out_size)
{
    const float* x  = (const float*)d_in[0];
    const float* Wq = (const float*)d_in[1];
    const float* Wk = (const float*)d_in[2];
    const float* Wv = (const float*)d_in[3];
    const float* Wo = (const float*)d_in[4];
    float* out = (float*)d_out;

    float *q, *k, *v, *ao, *ct, *st;
    cudaGetSymbolAddress((void**)&q,  g_q);
    cudaGetSymbolAddress((void**)&k,  g_k);
    cudaGetSymbolAddress((void**)&v,  g_v);
    cudaGetSymbolAddress((void**)&ao, g_ao);
    cudaGetSymbolAddress((void**)&ct, g_cos);
    cudaGetSymbolAddress((void**)&st, g_sin);

    __nv_bfloat16 *xhi, *xlo, *aohi, *aolo;
    __nv_bfloat16 *wqh, *wql, *wkh, *wkl, *wvh, *wvl, *woh, *wol;
    __nv_bfloat16 *qhi, *qlo, *khi, *klo, *vthi, *vtlo;
    cudaGetSymbolAddress((void**)&xhi,  g_xhi);
    cudaGetSymbolAddress((void**)&xlo,  g_xlo);
    cudaGetSymbolAddress((void**)&aohi, g_aohi);
    cudaGetSymbolAddress((void**)&aolo, g_aolo);
    cudaGetSymbolAddress((void**)&wqh,  g_wqt_hi);
    cudaGetSymbolAddress((void**)&wql,  g_wqt_lo);
    cudaGetSymbolAddress((void**)&wkh,  g_wkt_hi);
    cudaGetSymbolAddress((void**)&wkl,  g_wkt_lo);
    cudaGetSymbolAddress((void**)&wvh,  g_wvt_hi);
    cudaGetSymbolAddress((void**)&wvl,  g_wvt_lo);
    cudaGetSymbolAddress((void**)&woh,  g_wot_hi);
    cudaGetSymbolAddress((void**)&wol,  g_wot_lo);
    cudaGetSymbolAddress((void**)&qhi,  g_qhi);
    cudaGetSymbolAddress((void**)&qlo,  g_qlo);
    cudaGetSymbolAddress((void**)&khi,  g_khi);
    cudaGetSymbolAddress((void**)&klo,  g_klo);
    cudaGetSymbolAddress((void**)&vthi, g_vthi);
    cudaGetSymbolAddress((void**)&vtlo, g_vtlo);

    cudaFuncSetAttribute(attn_hmma_kernel, cudaFuncAttributeMaxDynamicSharedMemorySize,
                         ATTN_SMEM);
    cudaFuncSetAttribute(mgemm_kernel, cudaFuncAttributeMaxDynamicSharedMemorySize,
                         GEMM_SMEM);

    const int nx = M_ * D_;
    dim3 tsb(32, 8);

    // #1..#5
    rope_table_kernel<<<(T_ * 64 + 255) / 256, 256>>>(ct, st);
    split_kernel<<<(nx + 255) / 256, 256>>>(x, xhi, xlo, nx, 1.0f);
    transpose_split_kernel<<<dim3((H_ * HD_) / 32,  D_ / 32), tsb>>>(Wq, wqh, wql, D_, H_ * HD_);
    transpose_split_kernel<<<dim3((KV_ * HD_) / 32, D_ / 32), tsb>>>(Wk, wkh, wkl, D_, KV_ * HD_);
    transpose_split_kernel<<<dim3((KV_ * HD_) / 32, D_ / 32), tsb>>>(Wv, wvh, wvl, D_, KV_ * HD_);

    // #6: profiled by ncu
    mgemm_kernel<<<dim3((H_ * HD_) / 128,  M_ / 128), 256, GEMM_SMEM>>>(
        xhi, xlo, wqh, wql, q, M_, H_ * HD_, D_);
    mgemm_kernel<<<dim3((KV_ * HD_) / 128, M_ / 128), 256, GEMM_SMEM>>>(
        xhi, xlo, wkh, wkl, k, M_, KV_ * HD_, D_);
    mgemm_kernel<<<dim3((KV_ * HD_) / 128, M_ / 128), 256, GEMM_SMEM>>>(
        xhi, xlo, wvh, wvl, v, M_, KV_ * HD_, D_);

    transpose_split_kernel<<<dim3(D_ / 32, (H_ * HD_) / 32), tsb>>>(Wo, woh, wol, H_ * HD_, D_);

    // RoPE then split attention operands
    rope_apply_kernel<<<(M_ * H_  * 64) / 256, 256>>>(q, ct, st, H_);
    rope_apply_kernel<<<(M_ * KV_ * 64) / 256, 256>>>(k, ct, st, KV_);
    const float qscale = 0.08838834764831845f;   // 1/sqrt(128)
    split_kernel<<<(M_ * H_ * HD_ + 255) / 256, 256>>>(q, qhi, qlo, M_ * H_ * HD_, qscale);
    split_kernel<<<(M_ * KV_ * HD_ + 255) / 256, 256>>>(k, khi, klo, M_ * KV_ * HD_, 1.0f);
    vtrans_split_kernel<<<dim3(T_ / 32, HD_ / 32, B_ * KV_), tsb>>>(v, vthi, vtlo);

    // HMMA flash attention
    attn_hmma_kernel<<<(T_ / 64) * B_ * H_, 256, ATTN_SMEM>>>(
        qhi, qlo, khi, klo, vthi, vtlo, ao);

    // output projection
    split_kernel<<<(nx + 255) / 256, 256>>>(ao, aohi, aolo, nx, 1.0f);
    mgemm_kernel<<<dim3(D_ / 128, M_ / 128), 256, GEMM_SMEM>>>(
        aohi, aolo, woh, wol, out, M_, D_, H_ * HD_);
}

// round 17
// speedup vs baseline: 1.5207x; 1.0229x over previous
#include <cuda_runtime.h>
#include <cuda_bf16.h>
#include <math.h>
#include <stdint.h>

// ---------------------------------------------------------------------------
// Problem constants
// ---------------------------------------------------------------------------
#define B_    2
#define T_    2048
#define D_    2048
#define H_    16
#define KV_   4
#define HD_   128
#define NREP_ 4
#define M_    (B_ * T_)          // 4096 rows

// ---------------------------------------------------------------------------
// Static device scratch (no cudaMalloc allowed)
// ---------------------------------------------------------------------------
__device__ float g_q [(size_t)M_ * (H_ * HD_)];
__device__ float g_k [(size_t)M_ * (KV_ * HD_)];
__device__ float g_v [(size_t)M_ * (KV_ * HD_)];
__device__ float g_cos[T_ * 64];
__device__ float g_sin[T_ * 64];

__device__ __nv_bfloat16 g_xhi [(size_t)M_ * D_];
__device__ __nv_bfloat16 g_xlo [(size_t)M_ * D_];
__device__ __nv_bfloat16 g_aohi[(size_t)M_ * D_];
__device__ __nv_bfloat16 g_aolo[(size_t)M_ * D_];
__device__ __nv_bfloat16 g_wqt_hi[(size_t)(H_ * HD_) * D_];
__device__ __nv_bfloat16 g_wqt_lo[(size_t)(H_ * HD_) * D_];
__device__ __nv_bfloat16 g_wkt_hi[(size_t)(KV_ * HD_) * D_];
__device__ __nv_bfloat16 g_wkt_lo[(size_t)(KV_ * HD_) * D_];
__device__ __nv_bfloat16 g_wvt_hi[(size_t)(KV_ * HD_) * D_];
__device__ __nv_bfloat16 g_wvt_lo[(size_t)(KV_ * HD_) * D_];
__device__ __nv_bfloat16 g_wot_hi[(size_t)D_ * (H_ * HD_)];
__device__ __nv_bfloat16 g_wot_lo[(size_t)D_ * (H_ * HD_)];
__device__ __nv_bfloat16 g_qhi[(size_t)M_ * (H_ * HD_)];
__device__ __nv_bfloat16 g_qlo[(size_t)M_ * (H_ * HD_)];
__device__ __nv_bfloat16 g_khi[(size_t)M_ * (KV_ * HD_)];
__device__ __nv_bfloat16 g_klo[(size_t)M_ * (KV_ * HD_)];
__device__ __nv_bfloat16 g_vthi[(size_t)B_ * KV_ * HD_ * T_];
__device__ __nv_bfloat16 g_vtlo[(size_t)B_ * KV_ * HD_ * T_];

// ---------------------------------------------------------------------------
// PTX helpers (all HW-validated by the passing rounds)
// ---------------------------------------------------------------------------
__device__ __forceinline__ uint32_t smem_to_u32(const void* p) {
    uint32_t a;
    asm("{ .reg .u64 t; cvta.to.shared.u64 t, %1; cvt.u32.u64 %0, t; }"
        : "=r"(a) : "l"(p));
    return a;
}

#define CP_ASYNC16(saddr, gptr) \
    asm volatile("cp.async.cg.shared.global [%0], [%1], 16;" \
                 :: "r"((uint32_t)(saddr)), "l"(gptr) : "memory")
#define CP_ASYNC_COMMIT() \
    asm volatile("cp.async.commit_group;" ::: "memory")
#define CP_ASYNC_WAIT0() \
    asm volatile("cp.async.wait_group 0;" ::: "memory")
#define CP_ASYNC_WAIT1() \
    asm volatile("cp.async.wait_group 1;" ::: "memory")

#define LDMX4(r, addr) \
    asm volatile("ldmatrix.sync.aligned.m8n8.x4.shared.b16 {%0,%1,%2,%3}, [%4];" \
                 : "=r"((r)[0]), "=r"((r)[1]), "=r"((r)[2]), "=r"((r)[3]) \
                 : "r"(addr))
#define LDMX2(r, addr) \
    asm volatile("ldmatrix.sync.aligned.m8n8.x2.shared.b16 {%0,%1}, [%2];" \
                 : "=r"((r)[0]), "=r"((r)[1]) : "r"(addr))

__device__ __forceinline__ void mma16816(float* d, const uint32_t* a, const uint32_t* b) {
    asm volatile(
        "mma.sync.aligned.m16n8k16.row.col.f32.bf16.bf16.f32 "
        "{%0,%1,%2,%3}, {%4,%5,%6,%7}, {%8,%9}, {%0,%1,%2,%3};"
        : "+f"(d[0]), "+f"(d[1]), "+f"(d[2]), "+f"(d[3])
        : "r"(a[0]), "r"(a[1]), "r"(a[2]), "r"(a[3]), "r"(b[0]), "r"(b[1]));
}

// ---------------------------------------------------------------------------
// RoPE tables
// ---------------------------------------------------------------------------
__global__ void rope_table_kernel(float* __restrict__ cosT, float* __restrict__ sinT)
{
    int idx = blockIdx.x * blockDim.x + threadIdx.x;
    if (idx >= T_ * 64) return;
    int t = idx >> 6;
    int j = idx & 63;
    double inv_freq = exp(-((double)(2 * j) / (double)HD_) * log(10000.0));
    double ang = (double)t * inv_freq;
    cosT[idx] = (float)cos(ang);
    sinT[idx] = (float)sin(ang);
}

// Fused RoPE + scale + bf16 hi/lo split
__global__ void rope_split_kernel(const float* __restrict__ x,
                                  const float* __restrict__ cosT,
                                  const float* __restrict__ sinT,
                                  __nv_bfloat16* __restrict__ hi,
                                  __nv_bfloat16* __restrict__ lo,
                                  int nh, float scale)
{
    int idx = blockIdx.x * blockDim.x + threadIdx.x;
    int total = M_ * nh * 64;
    if (idx >= total) return;
    int j    = idx & 63;
    int hrow = idx >> 6;
    int head = hrow % nh;
    int row  = hrow / nh;
    int t    = row & (T_ - 1);
    float c = cosT[t * 64 + j];
    float s = sinT[t * 64 + j];
    size_t o = (size_t)row * (nh * HD_) + head * HD_ + j;
    float a = x[o];
    float b = x[o + 64];
    float r0 = (a * c - b * s) * scale;
    float r1 = (b * c + a * s) * scale;
    __nv_bfloat16 h0 = __float2bfloat16(r0);
    __nv_bfloat16 h1 = __float2bfloat16(r1);
    hi[o]      = h0;
    lo[o]      = __float2bfloat16(r0 - __bfloat162float(h0));
    hi[o + 64] = h1;
    lo[o + 64] = __float2bfloat16(r1 - __bfloat162float(h1));
}

// Split fp32 -> (bf16 hi, bf16 lo)
__global__ void split_kernel(const float* __restrict__ src,
                             __nv_bfloat16* __restrict__ hi,
                             __nv_bfloat16* __restrict__ lo, int n, float scale)
{
    int i = blockIdx.x * blockDim.x + threadIdx.x;
    if (i >= n) return;
    float v = src[i] * scale;
    __nv_bfloat16 h = __float2bfloat16(v);
    hi[i] = h;
    lo[i] = __float2bfloat16(v - __bfloat162float(h));
}

// Transpose + split: W[K,N] fp32 -> Wt_hi/lo[N,K] bf16.
__global__ void transpose_split_kernel(const float* __restrict__ W,
                                       __nv_bfloat16* __restrict__ hi,
                                       __nv_bfloat16* __restrict__ lo,
                                       int K, int N)
{
    __shared__ float tile[32][33];
    int n0 = blockIdx.x * 32, k0 = blockIdx.y * 32;
    int tx = threadIdx.x, ty = threadIdx.y;
#pragma unroll
    for (int i = 0; i < 32; i += 8)
        tile[ty + i][tx] = W[(size_t)(k0 + ty + i) * N + n0 + tx];
    __syncthreads();
#pragma unroll
    for (int i = 0; i < 32; i += 8) {
        float v = tile[tx][ty + i];
        __nv_bfloat16 h = __float2bfloat16(v);
        size_t o = (size_t)(n0 + ty + i) * K + k0 + tx;
        hi[o] = h;
        lo[o] = __float2bfloat16(v - __bfloat162float(h));
    }
}

// V transpose+split per head: g_v -> [(b,g,hd)][t] bf16 hi/lo
__global__ void vtrans_split_kernel(const float* __restrict__ V,
                                    __nv_bfloat16* __restrict__ hi,
                                    __nv_bfloat16* __restrict__ lo)
{
    __shared__ float tile[32][33];
    int t0 = blockIdx.x * 32, d0 = blockIdx.y * 32;
    int bg = blockIdx.z;
    int b = bg / KV_, g = bg % KV_;
    int tx = threadIdx.x, ty = threadIdx.y;
#pragma unroll
    for (int i = 0; i < 32; i += 8)
        tile[ty + i][tx] = V[(size_t)(b * T_ + t0 + ty + i) * (KV_ * HD_) + g * HD_ + d0 + tx];
    __syncthreads();
#pragma unroll
    for (int i = 0; i < 32; i += 8) {
        float v = tile[tx][ty + i];
        __nv_bfloat16 h = __float2bfloat16(v);
        size_t o = ((size_t)bg * HD_ + d0 + ty + i) * T_ + t0 + tx;
        hi[o] = h;
        lo[o] = __float2bfloat16(v - __bfloat162float(h));
    }
}

// ---------------------------------------------------------------------------
// HMMA GEMM (unchanged from the passing version)
// ---------------------------------------------------------------------------
#define GPITCH 40
#define GTILEB (128 * GPITCH * 2)
#define GSTAGE (4 * GTILEB)
#define GEMM_SMEM (2 * GSTAGE)             // 81920 bytes

__global__ __launch_bounds__(256, 2)
void mgemm_kernel(const __nv_bfloat16* __restrict__ Ahi, const __nv_bfloat16* __restrict__ Alo,
                  const __nv_bfloat16* __restrict__ Bhi, const __nv_bfloat16* __restrict__ Blo,
                  float* __restrict__ C, int Mdim, int Ndim, int Kdim)
{
    extern __shared__ __align__(16) char gsm[];
    const uint32_t sbase = smem_to_u32(gsm);
    const int tid  = threadIdx.x;
    const int wid  = tid >> 5;
    const int lane = tid & 31;
    const int bm = blockIdx.y * 128;
    const int bn = blockIdx.x * 128;
    const int wm = (wid >> 2) * 64;
    const int wn = (wid & 3) * 32;

    float acc[4][4][4];
#pragma unroll
    for (int mt = 0; mt < 4; mt++)
#pragma unroll
        for (int nt = 0; nt < 4; nt++)
#pragma unroll
            for (int e = 0; e < 4; e++) acc[mt][nt][e] = 0.f;

    const int nchunk = Kdim / 32;
    {
        const uint32_t st = sbase;
#pragma unroll
        for (int p = 0; p < 2; p++) {
            int idx = tid + 256 * p;
            int r = idx >> 2, q = idx & 3;
            uint32_t soff = (uint32_t)(r * 80 + q * 16);
            size_t ga = (size_t)(bm + r) * Kdim + q * 8;
            size_t gb = (size_t)(bn + r) * Kdim + q * 8;
            CP_ASYNC16(st + 0 * GTILEB + soff, Ahi + ga);
            CP_ASYNC16(st + 1 * GTILEB + soff, Alo + ga);
            CP_ASYNC16(st + 2 * GTILEB + soff, Bhi + gb);
            CP_ASYNC16(st + 3 * GTILEB + soff, Blo + gb);
        }
        CP_ASYNC_COMMIT();
    }

    const int arow = lane & 15;
    const int akq  = ((lane >> 4) & 1) * 8;
    const int brow = lane & 7;
    const int bkq  = ((lane >> 3) & 1) * 8;

    for (int c = 0; c < nchunk; c++) {
        if (c + 1 < nchunk) {
            const uint32_t st = sbase + ((c + 1) & 1) * GSTAGE;
            const int kc = (c + 1) * 32;
#pragma unroll
            for (int p = 0; p < 2; p++) {
                int idx = tid + 256 * p;
                int r = idx >> 2, q = idx & 3;
                uint32_t soff = (uint32_t)(r * 80 + q * 16);
                size_t ga = (size_t)(bm + r) * Kdim + kc + q * 8;
                size_t gb = (size_t)(bn + r) * Kdim + kc + q * 8;
                CP_ASYNC16(st + 0 * GTILEB + soff, Ahi + ga);
                CP_ASYNC16(st + 1 * GTILEB + soff, Alo + ga);
                CP_ASYNC16(st + 2 * GTILEB + soff, Bhi + gb);
                CP_ASYNC16(st + 3 * GTILEB + soff, Blo + gb);
            }
            CP_ASYNC_COMMIT();
            CP_ASYNC_WAIT1();
        } else {
            CP_ASYNC_WAIT0();
        }
        __syncthreads();

        const uint32_t st = sbase + (c & 1) * GSTAGE;
#pragma unroll
        for (int ks = 0; ks < 2; ks++) {
            uint32_t ahi[4][4], alo[4][4];
#pragma unroll
            for (int mt = 0; mt < 4; mt++) {
                uint32_t ad = st + (uint32_t)(((wm + mt * 16 + arow) * GPITCH
                                               + ks * 16 + akq) * 2);
                LDMX4(ahi[mt], ad);
                LDMX4(alo[mt], ad + GTILEB);
            }
            uint32_t bhi[4][2], blo[4][2];
#pragma unroll
            for (int nt = 0; nt < 4; nt++) {
                uint32_t bd = st + 2 * GTILEB
                            + (uint32_t)(((wn + nt * 8 + brow) * GPITCH
                                          + ks * 16 + bkq) * 2);
                LDMX2(bhi[nt], bd);
                LDMX2(blo[nt], bd + GTILEB);
            }
#pragma unroll
            for (int mt = 0; mt < 4; mt++)
#pragma unroll
                for (int nt = 0; nt < 4; nt++) {
                    mma16816(acc[mt][nt], ahi[mt], bhi[nt]);
                    mma16816(acc[mt][nt], ahi[mt], blo[nt]);
                    mma16816(acc[mt][nt], alo[mt], bhi[nt]);
                }
        }
        __syncthreads();
    }

    const int groupID = lane >> 2;
    const int tig     = lane & 3;
#pragma unroll
    for (int mt = 0; mt < 4; mt++) {
        int row0 = bm + wm + mt * 16 + groupID;
#pragma unroll
        for (int nt = 0; nt < 4; nt++) {
            int col = bn + wn + nt * 8 + tig * 2;
            *(float2*)(C + (size_t)row0 * Ndim + col) =
                make_float2(acc[mt][nt][0], acc[mt][nt][1]);
            *(float2*)(C + (size_t)(row0 + 8) * Ndim + col) =
                make_float2(acc[mt][nt][2], acc[mt][nt][3]);
        }
    }
}

// ---------------------------------------------------------------------------
// HMMA flash attention (causal, GQA). Epilogue emits bf16 hi/lo directly
// (packed bf16x2 stores; column pairs are contiguous and 4B-aligned).
// ---------------------------------------------------------------------------
#define AQP 136
#define AVP 72
#define ASP 68
#define A_QHI 0
#define A_QLO 17408
#define A_K(buf, part) (34816 + ((buf) * 2 + (part)) * 17408)
#define A_VT(buf, part) (104448 + ((buf) * 2 + (part)) * 18432)
#define A_SS  178176
#define A_PHI 195584
#define A_PLO 204800
#define A_M   214016
#define A_L   214272
#define A_A   214528
#define ATTN_SMEM 214784

__global__ __launch_bounds__(256)
void attn_hmma_kernel(const __nv_bfloat16* __restrict__ Qhi, const __nv_bfloat16* __restrict__ Qlo,
                      const __nv_bfloat16* __restrict__ Khi, const __nv_bfloat16* __restrict__ Klo,
                      const __nv_bfloat16* __restrict__ VThi, const __nv_bfloat16* __restrict__ VTlo,
                      __nv_bfloat16* __restrict__ Ohi, __nv_bfloat16* __restrict__ Olo)
{
    const int nQ  = T_ / 64;
    const int bid = blockIdx.x;
    const int bh  = bid / nQ;
    const int qi  = (nQ - 1) - (bid % nQ);
    const int b   = bh / H_;
    const int h   = bh % H_;
    const int g   = h / NREP_;
    const int q0  = qi * 64;
    const int bg  = b * KV_ + g;

    extern __shared__ __align__(16) char asmem[];
    const uint32_t sb = smem_to_u32(asmem);
    float* Ss  = (float*)(asmem + A_SS);
    float* m_s = (float*)(asmem + A_M);
    float* l_s = (float*)(asmem + A_L);
    float* a_s = (float*)(asmem + A_A);
    __nv_bfloat16* Phi = (__nv_bfloat16*)(asmem + A_PHI);
    __nv_bfloat16* Plo = (__nv_bfloat16*)(asmem + A_PLO);

    const int tid  = threadIdx.x;
    const int w    = tid >> 5;
    const int lane = tid & 31;
    const int groupID = lane >> 2;
    const int tig     = lane & 3;
    const int arow = lane & 15, akq = ((lane >> 4) & 1) * 8;
    const int brow = lane & 7,  bkq = ((lane >> 3) & 1) * 8;
    const float NEG = -1e30f;

    {
#pragma unroll
        for (int p = 0; p < 4; p++) {
            int it = tid + 256 * p;
            int r = it >> 4, q = it & 15;
            size_t src = (size_t)(b * T_ + q0 + r) * (H_ * HD_) + h * HD_ + q * 8;
            CP_ASYNC16(sb + A_QHI + r * 272 + q * 16, Qhi + src);
            CP_ASYNC16(sb + A_QLO + r * 272 + q * 16, Qlo + src);
        }
#pragma unroll
        for (int p = 0; p < 4; p++) {
            int it = tid + 256 * p;
            int r = it >> 4, q = it & 15;
            size_t src = (size_t)(b * T_ + r) * (KV_ * HD_) + g * HD_ + q * 8;
            CP_ASYNC16(sb + A_K(0, 0) + r * 272 + q * 16, Khi + src);
            CP_ASYNC16(sb + A_K(0, 1) + r * 272 + q * 16, Klo + src);
        }
#pragma unroll
        for (int p = 0; p < 4; p++) {
            int it = tid + 256 * p;
            int r = it >> 3, q = it & 7;
            size_t src = ((size_t)bg * HD_ + r) * T_ + q * 8;
            CP_ASYNC16(sb + A_VT(0, 0) + r * 144 + q * 16, VThi + src);
            CP_ASYNC16(sb + A_VT(0, 1) + r * 144 + q * 16, VTlo + src);
        }
        CP_ASYNC_COMMIT();
    }
    if (tid < 64) { m_s[tid] = NEG; l_s[tid] = 0.f; }

    float oacc[2][4][4];
#pragma unroll
    for (int mt = 0; mt < 2; mt++)
#pragma unroll
        for (int nt = 0; nt < 4; nt++)
#pragma unroll
            for (int e = 0; e < 4; e++) oacc[mt][nt][e] = 0.f;

    const int wm2 = (w >> 2) * 32;
    const int wn2 = (w & 3) * 16;
    const int wnO = (w & 3) * 32;

    const int nkv = qi + 1;
    for (int kt = 0; kt < nkv; kt++) {
        if (kt + 1 < nkv) {
            const int bufn = (kt + 1) & 1;
            const int k0n = (kt + 1) * 64;
#pragma unroll
            for (int p = 0; p < 4; p++) {
                int it = tid + 256 * p;
                int r = it >> 4, q = it & 15;
                size_t src = (size_t)(b * T_ + k0n + r) * (KV_ * HD_) + g * HD_ + q * 8;
                CP_ASYNC16(sb + A_K(bufn, 0) + r * 272 + q * 16, Khi + src);
                CP_ASYNC16(sb + A_K(bufn, 1) + r * 272 + q * 16, Klo + src);
            }
#pragma unroll
            for (int p = 0; p < 4; p++) {
                int it = tid + 256 * p;
                int r = it >> 3, q = it & 7;
                size_t src = ((size_t)bg * HD_ + r) * T_ + k0n + q * 8;
                CP_ASYNC16(sb + A_VT(bufn, 0) + r * 144 + q * 16, VThi + src);
                CP_ASYNC16(sb + A_VT(bufn, 1) + r * 144 + q * 16, VTlo + src);
            }
            CP_ASYNC_COMMIT();
            CP_ASYNC_WAIT1();
        } else {
            CP_ASYNC_WAIT0();
        }
        __syncthreads();

        const uint32_t kb = sb + A_K(kt & 1, 0);
        const uint32_t vb = sb + A_VT(kt & 1, 0);

        float sacc[2][2][4];
#pragma unroll
        for (int mt = 0; mt < 2; mt++)
#pragma unroll
            for (int nt = 0; nt < 2; nt++)
#pragma unroll
                for (int e = 0; e < 4; e++) sacc[mt][nt][e] = 0.f;

#pragma unroll
        for (int ks = 0; ks < 8; ks++) {
            uint32_t qh[2][4], ql[2][4];
#pragma unroll
            for (int mt = 0; mt < 2; mt++) {
                uint32_t ad = sb + A_QHI
                    + (uint32_t)(((wm2 + mt * 16 + arow) * AQP + ks * 16 + akq) * 2);
                LDMX4(qh[mt], ad);
                LDMX4(ql[mt], ad + (A_QLO - A_QHI));
            }
            uint32_t kh[2][2], kl[2][2];
#pragma unroll
            for (int nt = 0; nt < 2; nt++) {
                uint32_t bd = kb
                    + (uint32_t)(((wn2 + nt * 8 + brow) * AQP + ks * 16 + bkq) * 2);
                LDMX2(kh[nt], bd);
                LDMX2(kl[nt], bd + 17408);
            }
#pragma unroll
            for (int mt = 0; mt < 2; mt++)
#pragma unroll
                for (int nt = 0; nt < 2; nt++) {
                    mma16816(sacc[mt][nt], qh[mt], kh[nt]);
                    mma16816(sacc[mt][nt], qh[mt], kl[nt]);
                    mma16816(sacc[mt][nt], ql[mt], kh[nt]);
                }
        }

#pragma unroll
        for (int mt = 0; mt < 2; mt++) {
            int r0 = wm2 + mt * 16 + groupID;
#pragma unroll
            for (int nt = 0; nt < 2; nt++) {
                int c = wn2 + nt * 8 + tig * 2;
                float v0 = sacc[mt][nt][0], v1 = sacc[mt][nt][1];
                float v2 = sacc[mt][nt][2], v3 = sacc[mt][nt][3];
                if (kt == qi) {
                    if (c     > r0)     v0 = NEG;
                    if (c + 1 > r0)     v1 = NEG;
                    if (c     > r0 + 8) v2 = NEG;
                    if (c + 1 > r0 + 8) v3 = NEG;
                }
                Ss[r0 * ASP + c]           = v0;
                Ss[r0 * ASP + c + 1]       = v1;
                Ss[(r0 + 8) * ASP + c]     = v2;
                Ss[(r0 + 8) * ASP + c + 1] = v3;
            }
        }
        __syncthreads();

        for (int rl = 0; rl < 8; rl++) {
            int r = w * 8 + rl;
            float x0 = Ss[r * ASP + lane];
            float x1 = Ss[r * ASP + lane + 32];
            float mx = fmaxf(x0, x1);
#pragma unroll
            for (int off = 16; off; off >>= 1)
                mx = fmaxf(mx, __shfl_xor_sync(0xffffffffu, mx, off));
            float mold = m_s[r];
            float mnew = fmaxf(mold, mx);
            float e0 = __expf(x0 - mnew);
            float e1 = __expf(x1 - mnew);
            __nv_bfloat16 h0 = __float2bfloat16(e0);
            __nv_bfloat16 h1 = __float2bfloat16(e1);
            Phi[r * AVP + lane]      = h0;
            Plo[r * AVP + lane]      = __float2bfloat16(e0 - __bfloat162float(h0));
            Phi[r * AVP + lane + 32] = h1;
            Plo[r * AVP + lane + 32] = __float2bfloat16(e1 - __bfloat162float(h1));
            float sum = e0 + e1;
#pragma unroll
            for (int off = 16; off; off >>= 1)
                sum += __shfl_xor_sync(0xffffffffu, sum, off);
            if (lane == 0) {
                float alpha = __expf(mold - mnew);
                l_s[r] = l_s[r] * alpha + sum;
                m_s[r] = mnew;
                a_s[r] = alpha;
            }
        }
        __syncthreads();

#pragma unroll
        for (int mt = 0; mt < 2; mt++) {
            float a0 = a_s[wm2 + mt * 16 + groupID];
            float a1 = a_s[wm2 + mt * 16 + groupID + 8];
#pragma unroll
            for (int nt = 0; nt < 4; nt++) {
                oacc[mt][nt][0] *= a0; oacc[mt][nt][1] *= a0;
                oacc[mt][nt][2] *= a1; oacc[mt][nt][3] *= a1;
            }
        }
#pragma unroll
        for (int ks = 0; ks < 4; ks++) {
            uint32_t ph[2][4], pl[2][4];
#pragma unroll
            for (int mt = 0; mt < 2; mt++) {
                uint32_t ad = sb + A_PHI
                    + (uint32_t)(((wm2 + mt * 16 + arow) * AVP + ks * 16 + akq) * 2);
                LDMX4(ph[mt], ad);
                LDMX4(pl[mt], ad + (A_PLO - A_PHI));
            }
            uint32_t vh[4][2], vl[4][2];
#pragma unroll
            for (int nt = 0; nt < 4; nt++) {
                uint32_t bd = vb
                    + (uint32_t)(((wnO + nt * 8 + brow) * AVP + ks * 16 + bkq) * 2);
                LDMX2(vh[nt], bd);
                LDMX2(vl[nt], bd + 18432);
            }
#pragma unroll
            for (int mt = 0; mt < 2; mt++)
#pragma unroll
                for (int nt = 0; nt < 4; nt++) {
                    mma16816(oacc[mt][nt], ph[mt], vh[nt]);
                    mma16816(oacc[mt][nt], ph[mt], vl[nt]);
                    mma16816(oacc[mt][nt], pl[mt], vh[nt]);
                }
        }
        __syncthreads();
    }

    // ---- epilogue: normalize, split to bf16 hi/lo, packed bf16x2 stores ----
#pragma unroll
    for (int mt = 0; mt < 2; mt++) {
        int rl0 = wm2 + mt * 16 + groupID;
        float inv0 = 1.0f / l_s[rl0];
        float inv1 = 1.0f / l_s[rl0 + 8];
#pragma unroll
        for (int nt = 0; nt < 4; nt++) {
            int c = wnO + nt * 8 + tig * 2;
            size_t off  = (size_t)(b * T_ + q0 + rl0) * (H_ * HD_) + h * HD_ + c;
            size_t off8 = off + (size_t)8 * (H_ * HD_);
            float u0 = oacc[mt][nt][0] * inv0, u1 = oacc[mt][nt][1] * inv0;
            float u2 = oacc[mt][nt][2] * inv1, u3 = oacc[mt][nt][3] * inv1;
            __nv_bfloat16 h0 = __float2bfloat16(u0);
            __nv_bfloat16 h1 = __float2bfloat16(u1);
            __nv_bfloat16 h2 = __float2bfloat16(u2);
            __nv_bfloat16 h3 = __float2bfloat16(u3);
            *(__nv_bfloat162*)(Ohi + off)  = __nv_bfloat162(h0, h1);
            *(__nv_bfloat162*)(Ohi + off8) = __nv_bfloat162(h2, h3);
            *(__nv_bfloat162*)(Olo + off)  = __nv_bfloat162(
                __float2bfloat16(u0 - __bfloat162float(h0)),
                __float2bfloat16(u1 - __bfloat162float(h1)));
            *(__nv_bfloat162*)(Olo + off8) = __nv_bfloat162(
                __float2bfloat16(u2 - __bfloat162float(h2)),
                __float2bfloat16(u3 - __bfloat162float(h3)));
        }
    }
}

// ---------------------------------------------------------------------------
// Host orchestration. mgemms occupy launch slots 5-7 so the ncu capture
// (-s 5 -c 1, indexing ambiguity +-1) lands on a GEMM.
// ---------------------------------------------------------------------------
extern "C" void kernel_launch(void* const* d_in, const int* in_sizes, int n_in,
                              void* d_out, int out_size)
{
    const float* x  = (const float*)d_in[0];
    const float* Wq = (const float*)d_in[1];
    const float* Wk = (const float*)d_in[2];
    const float* Wv = (const float*)d_in[3];
    const float* Wo = (const float*)d_in[4];
    float* out = (float*)d_out;

    float *q, *k, *v, *ct, *st;
    cudaGetSymbolAddress((void**)&q,  g_q);
    cudaGetSymbolAddress((void**)&k,  g_k);
    cudaGetSymbolAddress((void**)&v,  g_v);
    cudaGetSymbolAddress((void**)&ct, g_cos);
    cudaGetSymbolAddress((void**)&st, g_sin);

    __nv_bfloat16 *xhi, *xlo, *aohi, *aolo;
    __nv_bfloat16 *wqh, *wql, *wkh, *wkl, *wvh, *wvl, *woh, *wol;
    __nv_bfloat16 *qhi, *qlo, *khi, *klo, *vthi, *vtlo;
    cudaGetSymbolAddress((void**)&xhi,  g_xhi);
    cudaGetSymbolAddress((void**)&xlo,  g_xlo);
    cudaGetSymbolAddress((void**)&aohi, g_aohi);
    cudaGetSymbolAddress((void**)&aolo, g_aolo);
    cudaGetSymbolAddress((void**)&wqh,  g_wqt_hi);
    cudaGetSymbolAddress((void**)&wql,  g_wqt_lo);
    cudaGetSymbolAddress((void**)&wkh,  g_wkt_hi);
    cudaGetSymbolAddress((void**)&wkl,  g_wkt_lo);
    cudaGetSymbolAddress((void**)&wvh,  g_wvt_hi);
    cudaGetSymbolAddress((void**)&wvl,  g_wvt_lo);
    cudaGetSymbolAddress((void**)&woh,  g_wot_hi);
    cudaGetSymbolAddress((void**)&wol,  g_wot_lo);
    cudaGetSymbolAddress((void**)&qhi,  g_qhi);
    cudaGetSymbolAddress((void**)&qlo,  g_qlo);
    cudaGetSymbolAddress((void**)&khi,  g_khi);
    cudaGetSymbolAddress((void**)&klo,  g_klo);
    cudaGetSymbolAddress((void**)&vthi, g_vthi);
    cudaGetSymbolAddress((void**)&vtlo, g_vtlo);

    cudaFuncSetAttribute(attn_hmma_kernel, cudaFuncAttributeMaxDynamicSharedMemorySize,
                         ATTN_SMEM);
    cudaFuncSetAttribute(mgemm_kernel, cudaFuncAttributeMaxDynamicSharedMemorySize,
                         GEMM_SMEM);

    const int nx = M_ * D_;
    dim3 tsb(32, 8);

    // #1..#4: operand prep for QKV GEMMs
    split_kernel<<<(nx + 255) / 256, 256>>>(x, xhi, xlo, nx, 1.0f);
    transpose_split_kernel<<<dim3((H_ * HD_) / 32,  D_ / 32), tsb>>>(Wq, wqh, wql, D_, H_ * HD_);
    transpose_split_kernel<<<dim3((KV_ * HD_) / 32, D_ / 32), tsb>>>(Wk, wkh, wkl, D_, KV_ * HD_);
    transpose_split_kernel<<<dim3((KV_ * HD_) / 32, D_ / 32), tsb>>>(Wv, wvh, wvl, D_, KV_ * HD_);

    // #5..#7: QKV projections (ncu capture slot lands here)
    mgemm_kernel<<<dim3((H_ * HD_) / 128,  M_ / 128), 256, GEMM_SMEM>>>(
        xhi, xlo, wqh, wql, q, M_, H_ * HD_, D_);
    mgemm_kernel<<<dim3((KV_ * HD_) / 128, M_ / 128), 256, GEMM_SMEM>>>(
        xhi, xlo, wkh, wkl, k, M_, KV_ * HD_, D_);
    mgemm_kernel<<<dim3((KV_ * HD_) / 128, M_ / 128), 256, GEMM_SMEM>>>(
        xhi, xlo, wvh, wvl, v, M_, KV_ * HD_, D_);

    // remaining prep
    rope_table_kernel<<<(T_ * 64 + 255) / 256, 256>>>(ct, st);
    transpose_split_kernel<<<dim3(D_ / 32, (H_ * HD_) / 32), tsb>>>(Wo, woh, wol, H_ * HD_, D_);

    const float qscale = 0.08838834764831845f;   // 1/sqrt(128)
    rope_split_kernel<<<(M_ * H_  * 64 + 255) / 256, 256>>>(q, ct, st, qhi, qlo, H_,  qscale);
    rope_split_kernel<<<(M_ * KV_ * 64 + 255) / 256, 256>>>(k, ct, st, khi, klo, KV_, 1.0f);
    vtrans_split_kernel<<<dim3(T_ / 32, HD_ / 32, B_ * KV_), tsb>>>(v, vthi, vtlo);

    // HMMA flash attention -> bf16 hi/lo directly
    attn_hmma_kernel<<<(T_ / 64) * B_ * H_, 256, ATTN_SMEM>>>(
        qhi, qlo, khi, klo, vthi, vtlo, aohi, aolo);

    // output projection
    mgemm_kernel<<<dim3(D_ / 128, M_ / 128), 256, GEMM_SMEM>>>(
        aohi, aolo, woh, wol, out, M_, D_, H_ * HD_);
}